// round 1
// baseline (speedup 1.0000x reference)
#include <cuda_runtime.h>

#define NN 512
#define NPAIRS 130816   // 512*511/2

// ---------------- device scratch (no allocations allowed) ----------------
__device__ float2 g_csU[NPAIRS];
__device__ float2 g_csV[NPAIRS];
__device__ float  g_U [NN * NN];   // delta_U[a] * RU[a][k]          (row-major [a][k])
__device__ float  g_Vs[NN * NN];   // sigma[k]*delta_V[k]*RV[k][b]   (row-major [k][b])
__device__ float  g_W [NN * NN];   // W[o][k]                        (row-major [o][k])

// ---------------- 1) cos/sin precompute ----------------
__global__ void setup_cs_kernel(const float* __restrict__ phiU,
                                const float* __restrict__ phiV) {
    int i = blockIdx.x * blockDim.x + threadIdx.x;
    if (i < NPAIRS) {
        float s, c;
        sincosf(phiU[i], &s, &c);
        g_csU[i] = make_float2(c, s);
        sincosf(phiV[i], &s, &c);
        g_csV[i] = make_float2(c, s);
    }
}

// ---------------- 2) Givens-mesh reconstruction ----------------
// Each thread owns ONE column of the matrix (columns are fully independent
// under row rotations). Column lives in shared memory with a padded stride
// so lane t / row r maps to bank (t + r) % 32  -> conflict-free.
// During pivot i, row i is carried in register A; the dependence chain per
// rotation step is a single FFMA.
#define RCOLS   16          // columns (=threads) per CTA; 16*513*4 = 32832 B static smem
#define RSTRIDE 513

__global__ void reconstruct_kernel(const float* __restrict__ dU,
                                   const float* __restrict__ dV,
                                   const float* __restrict__ sigma) {
    __shared__ float sh[RCOLS * RSTRIDE];

    const int mat     = blockIdx.x >> 5;          // 0 = U, 1 = V  (32 CTAs each)
    const int colbase = (blockIdx.x & 31) * RCOLS;
    const int t       = threadIdx.x;              // 0..15
    const int col     = colbase + t;

    const float2* __restrict__ cs = mat ? g_csV : g_csU;
    float* myc = &sh[t * RSTRIDE];

    // identity column
    for (int r = 0; r < NN; r++) myc[r] = (r == col) ? 1.0f : 0.0f;

    int k = 0;
    for (int i = 0; i < NN - 1; i++) {
        float A = myc[i];                 // register-resident pivot row entry
        #pragma unroll 4
        for (int j = NN - 1; j > i; j--) {
            float2 p  = __ldg(&cs[k]); k++;       // (c, s) — uniform, off-chain
            float  uj = myc[j];                    // off-chain LDS
            myc[j] = p.y * A + p.x * uj;           // new u[j] (uses old A)
            A      = p.x * A - p.y * uj;           // chain: 1 FFMA deep
        }
        myc[i] = A;
    }

    // scale + write back row-major (coalesced across threads)
    if (mat == 0) {
        for (int r = 0; r < NN; r++)
            g_U[r * NN + col] = dU[r] * myc[r];
    } else {
        for (int r = 0; r < NN; r++)
            g_Vs[r * NN + col] = sigma[r] * dV[r] * myc[r];
    }
}

// ---------------- 3) W = U @ (sigma*delta_V * V)   (512x512x512, tiny) ----------------
__global__ void wgemm_kernel() {
    __shared__ float As[32][33];
    __shared__ float Bs[32][33];
    const int tx = threadIdx.x, ty = threadIdx.y;
    const int a = blockIdx.y * 32 + ty;    // output row
    const int b = blockIdx.x * 32 + tx;    // output col
    float acc = 0.0f;
    for (int kt = 0; kt < NN; kt += 32) {
        As[ty][tx] = g_U [a * NN + kt + tx];
        Bs[ty][tx] = g_Vs[(kt + ty) * NN + b];
        __syncthreads();
        #pragma unroll
        for (int kk = 0; kk < 32; kk++)
            acc += As[ty][kk] * Bs[kk][tx];
        __syncthreads();
    }
    g_W[a * NN + b] = acc;
}

// ---------------- 4) out = x @ W^T  (M=32768, N=512, K=512, fp32) ----------------
// Classic 128x128 CTA tile, BK=16, 256 threads, 8x8 micro-tile per thread.
// Both operands are K-contiguous (NT gemm).
__global__ void __launch_bounds__(256) sgemm_kernel(const float* __restrict__ A,
                                                    float* __restrict__ C) {
    __shared__ float As[16][132];
    __shared__ float Bs[16][132];
    const float* __restrict__ B = g_W;

    const int tid = threadIdx.x;
    const int m0  = blockIdx.y * 128;
    const int n0  = blockIdx.x * 128;
    const int tx  = tid & 15;      // 0..15  -> n direction
    const int ty  = tid >> 4;      // 0..15  -> m direction
    const int lrow = tid >> 2;     // 0..63
    const int lcol = (tid & 3) << 2;

    const float* Ap = A + (m0 + lrow) * NN + lcol;
    const float* Bp = B + (n0 + lrow) * NN + lcol;

    float acc[8][8];
    #pragma unroll
    for (int i = 0; i < 8; i++)
        #pragma unroll
        for (int j = 0; j < 8; j++) acc[i][j] = 0.0f;

    for (int k0 = 0; k0 < NN; k0 += 16) {
        float4 a0 = *(const float4*)(Ap + k0);
        float4 a1 = *(const float4*)(Ap + 64 * NN + k0);
        float4 b0 = *(const float4*)(Bp + k0);
        float4 b1 = *(const float4*)(Bp + 64 * NN + k0);

        As[lcol + 0][lrow]      = a0.x; As[lcol + 1][lrow]      = a0.y;
        As[lcol + 2][lrow]      = a0.z; As[lcol + 3][lrow]      = a0.w;
        As[lcol + 0][lrow + 64] = a1.x; As[lcol + 1][lrow + 64] = a1.y;
        As[lcol + 2][lrow + 64] = a1.z; As[lcol + 3][lrow + 64] = a1.w;
        Bs[lcol + 0][lrow]      = b0.x; Bs[lcol + 1][lrow]      = b0.y;
        Bs[lcol + 2][lrow]      = b0.z; Bs[lcol + 3][lrow]      = b0.w;
        Bs[lcol + 0][lrow + 64] = b1.x; Bs[lcol + 1][lrow + 64] = b1.y;
        Bs[lcol + 2][lrow + 64] = b1.z; Bs[lcol + 3][lrow + 64] = b1.w;
        __syncthreads();

        #pragma unroll
        for (int kk = 0; kk < 16; kk++) {
            float4 av0 = *(const float4*)&As[kk][ty * 8];
            float4 av1 = *(const float4*)&As[kk][ty * 8 + 4];
            float4 bv0 = *(const float4*)&Bs[kk][tx * 8];
            float4 bv1 = *(const float4*)&Bs[kk][tx * 8 + 4];
            float a[8] = {av0.x, av0.y, av0.z, av0.w, av1.x, av1.y, av1.z, av1.w};
            float b[8] = {bv0.x, bv0.y, bv0.z, bv0.w, bv1.x, bv1.y, bv1.z, bv1.w};
            #pragma unroll
            for (int i = 0; i < 8; i++)
                #pragma unroll
                for (int j = 0; j < 8; j++)
                    acc[i][j] += a[i] * b[j];
        }
        __syncthreads();
    }

    #pragma unroll
    for (int i = 0; i < 8; i++) {
        int m = m0 + ty * 8 + i;
        *(float4*)&C[m * NN + n0 + tx * 8]     = make_float4(acc[i][0], acc[i][1], acc[i][2], acc[i][3]);
        *(float4*)&C[m * NN + n0 + tx * 8 + 4] = make_float4(acc[i][4], acc[i][5], acc[i][6], acc[i][7]);
    }
}

// ---------------- launch ----------------
extern "C" void kernel_launch(void* const* d_in, const int* in_sizes, int n_in,
                              void* d_out, int out_size) {
    const float* x     = (const float*)d_in[0];
    const float* phiU  = (const float*)d_in[1];
    const float* dU    = (const float*)d_in[2];
    const float* phiV  = (const float*)d_in[3];
    const float* dV    = (const float*)d_in[4];
    const float* sigma = (const float*)d_in[5];
    float* out = (float*)d_out;

    setup_cs_kernel<<<(NPAIRS + 255) / 256, 256>>>(phiU, phiV);
    reconstruct_kernel<<<64, RCOLS>>>(dU, dV, sigma);
    wgemm_kernel<<<dim3(16, 16), dim3(32, 32)>>>();
    sgemm_kernel<<<dim3(NN / 128, 32768 / 128), 256>>>(x, out);
}

// round 2
// speedup vs baseline: 2.6915x; 2.6915x over previous
#include <cuda_runtime.h>

#define NN 512
#define NPAIRS 130816   // 512*511/2
#define RSTRIDE 516     // column stride in smem floats (mult of 4 -> float4 aligned, conflict-free by phase)
#define RINGSZ 1024     // cs ring entries (float2) = 8KB
#define RINGMASK 1023

// ---------------- device scratch (no allocations allowed) ----------------
__device__ float2 g_csU[NPAIRS];
__device__ float2 g_csV[NPAIRS];
__device__ float  g_U [NN * NN];   // delta_U[a] * RU[a][k]          (row-major [a][k])
__device__ float  g_Vs[NN * NN];   // sigma[k]*delta_V[k]*RV[k][b]   (row-major [k][b])
__device__ float  g_W [NN * NN];   // W[o][k]                        (row-major [o][k])

// ---------------- 1) cos/sin precompute ----------------
__global__ void setup_cs_kernel(const float* __restrict__ phiU,
                                const float* __restrict__ phiV) {
    int i = blockIdx.x * blockDim.x + threadIdx.x;
    if (i < NPAIRS) {
        float s, c;
        sincosf(phiU[i], &s, &c);
        g_csU[i] = make_float2(c, s);
        sincosf(phiV[i], &s, &c);
        g_csV[i] = make_float2(c, s);
    }
}

// ---------------- 2) Givens-mesh reconstruction ----------------
// One warp per CTA; lane t owns column (colbase + t), resident in smem.
// (c,s) stream staged through an smem ring, refilled at pivot boundaries from
// a register prefetch buffer that is always one fill (512 entries) ahead, so
// global-load latency overlaps compute. Column processed 4 rows at a time via
// float4; the only serial dependence is the 1-FFMA-deep pivot-carry A.
__global__ void __launch_bounds__(32) reconstruct_kernel(const float* __restrict__ dU,
                                                         const float* __restrict__ dV,
                                                         const float* __restrict__ sigma) {
    extern __shared__ float sm[];
    float*  cols = sm;                                   // 32 * RSTRIDE floats
    float2* ring = (float2*)(sm + 32 * RSTRIDE);         // RINGSZ float2

    const int mat     = blockIdx.x >> 4;                 // 0 = U (CTAs 0..15), 1 = V
    const int colbase = (blockIdx.x & 15) * 32;
    const int t       = threadIdx.x;
    const int col     = colbase + t;

    const float2* __restrict__ cs = mat ? g_csV : g_csU;
    float* myc = cols + t * RSTRIDE;

    // identity column
    for (int r = 0; r < NN; r += 4) {
        float4 z = make_float4(0.f, 0.f, 0.f, 0.f);
        if (col >= r && col < r + 4) ((float*)&z)[col - r] = 1.0f;
        *(float4*)&myc[r] = z;
    }

    // ---- cs staging: prefetch one fill (512 entries) ahead in registers ----
    float2 pref[16];
    int next_load = 0, fill_pos = 0;
    #pragma unroll
    for (int q = 0; q < 16; q++) {
        int idx = next_load + q * 32 + t;
        if (idx > NPAIRS - 1) idx = NPAIRS - 1;
        pref[q] = __ldg(&cs[idx]);
    }
    next_load += 512;

    int k = 0;
    for (int i = 0; i < NN - 1; i++) {
        // top up ring so the whole pivot (<=511 steps) is staged
        while (fill_pos - k < 512 && fill_pos < NPAIRS) {
            #pragma unroll
            for (int q = 0; q < 16; q++)
                ring[(fill_pos + q * 32 + t) & RINGMASK] = pref[q];
            fill_pos += 512;
            #pragma unroll
            for (int q = 0; q < 16; q++) {
                int idx = next_load + q * 32 + t;
                if (idx > NPAIRS - 1) idx = NPAIRS - 1;
                pref[q] = __ldg(&cs[idx]);
            }
            next_load += 512;
            __syncwarp();
        }

        float A = myc[i];                 // register-resident pivot carry
        int j = 511;
        #pragma unroll 2
        for (; j - 3 >= i + 1; j -= 4) {  // jb = j-3 is always % 4 == 0
            float4 v = *(float4*)&myc[j - 3];
            float2 p;
            p = ring[(k + 0) & RINGMASK];
            { float u = v.w; v.w = fmaf(p.y, A, p.x * u); A = fmaf(p.x, A, -p.y * u); }
            p = ring[(k + 1) & RINGMASK];
            { float u = v.z; v.z = fmaf(p.y, A, p.x * u); A = fmaf(p.x, A, -p.y * u); }
            p = ring[(k + 2) & RINGMASK];
            { float u = v.y; v.y = fmaf(p.y, A, p.x * u); A = fmaf(p.x, A, -p.y * u); }
            p = ring[(k + 3) & RINGMASK];
            { float u = v.x; v.x = fmaf(p.y, A, p.x * u); A = fmaf(p.x, A, -p.y * u); }
            k += 4;
            *(float4*)&myc[j - 3] = v;
        }
        for (; j >= i + 1; j--) {
            float2 p = ring[k & RINGMASK]; k++;
            float u = myc[j];
            myc[j] = fmaf(p.y, A, p.x * u);
            A = fmaf(p.x, A, -p.y * u);
        }
        myc[i] = A;
    }

    // scale + write back row-major (coalesced across lanes)
    if (mat == 0) {
        for (int r = 0; r < NN; r++)
            g_U[r * NN + col] = __ldg(&dU[r]) * myc[r];
    } else {
        for (int r = 0; r < NN; r++)
            g_Vs[r * NN + col] = __ldg(&sigma[r]) * __ldg(&dV[r]) * myc[r];
    }
}

// ---------------- 3) W = U @ (sigma*delta_V * V)   (512x512x512, tiny) ----------------
__global__ void wgemm_kernel() {
    __shared__ float As[32][33];
    __shared__ float Bs[32][33];
    const int tx = threadIdx.x, ty = threadIdx.y;
    const int a = blockIdx.y * 32 + ty;    // output row
    const int b = blockIdx.x * 32 + tx;    // output col
    float acc = 0.0f;
    for (int kt = 0; kt < NN; kt += 32) {
        As[ty][tx] = g_U [a * NN + kt + tx];
        Bs[ty][tx] = g_Vs[(kt + ty) * NN + b];
        __syncthreads();
        #pragma unroll
        for (int kk = 0; kk < 32; kk++)
            acc += As[ty][kk] * Bs[kk][tx];
        __syncthreads();
    }
    g_W[a * NN + b] = acc;
}

// ---------------- 4) out = x @ W^T  (M=32768, N=512, K=512, fp32) ----------------
__global__ void __launch_bounds__(256) sgemm_kernel(const float* __restrict__ A,
                                                    float* __restrict__ C) {
    __shared__ float As[16][132];
    __shared__ float Bs[16][132];
    const float* __restrict__ B = g_W;

    const int tid = threadIdx.x;
    const int m0  = blockIdx.y * 128;
    const int n0  = blockIdx.x * 128;
    const int tx  = tid & 15;      // 0..15  -> n direction
    const int ty  = tid >> 4;      // 0..15  -> m direction
    const int lrow = tid >> 2;     // 0..63
    const int lcol = (tid & 3) << 2;

    const float* Ap = A + (m0 + lrow) * NN + lcol;
    const float* Bp = B + (n0 + lrow) * NN + lcol;

    float acc[8][8];
    #pragma unroll
    for (int i = 0; i < 8; i++)
        #pragma unroll
        for (int j = 0; j < 8; j++) acc[i][j] = 0.0f;

    for (int k0 = 0; k0 < NN; k0 += 16) {
        float4 a0 = *(const float4*)(Ap + k0);
        float4 a1 = *(const float4*)(Ap + 64 * NN + k0);
        float4 b0 = *(const float4*)(Bp + k0);
        float4 b1 = *(const float4*)(Bp + 64 * NN + k0);

        As[lcol + 0][lrow]      = a0.x; As[lcol + 1][lrow]      = a0.y;
        As[lcol + 2][lrow]      = a0.z; As[lcol + 3][lrow]      = a0.w;
        As[lcol + 0][lrow + 64] = a1.x; As[lcol + 1][lrow + 64] = a1.y;
        As[lcol + 2][lrow + 64] = a1.z; As[lcol + 3][lrow + 64] = a1.w;
        Bs[lcol + 0][lrow]      = b0.x; Bs[lcol + 1][lrow]      = b0.y;
        Bs[lcol + 2][lrow]      = b0.z; Bs[lcol + 3][lrow]      = b0.w;
        Bs[lcol + 0][lrow + 64] = b1.x; Bs[lcol + 1][lrow + 64] = b1.y;
        Bs[lcol + 2][lrow + 64] = b1.z; Bs[lcol + 3][lrow + 64] = b1.w;
        __syncthreads();

        #pragma unroll
        for (int kk = 0; kk < 16; kk++) {
            float4 av0 = *(const float4*)&As[kk][ty * 8];
            float4 av1 = *(const float4*)&As[kk][ty * 8 + 4];
            float4 bv0 = *(const float4*)&Bs[kk][tx * 8];
            float4 bv1 = *(const float4*)&Bs[kk][tx * 8 + 4];
            float a[8] = {av0.x, av0.y, av0.z, av0.w, av1.x, av1.y, av1.z, av1.w};
            float b[8] = {bv0.x, bv0.y, bv0.z, bv0.w, bv1.x, bv1.y, bv1.z, bv1.w};
            #pragma unroll
            for (int i = 0; i < 8; i++)
                #pragma unroll
                for (int j = 0; j < 8; j++)
                    acc[i][j] += a[i] * b[j];
        }
        __syncthreads();
    }

    #pragma unroll
    for (int i = 0; i < 8; i++) {
        int m = m0 + ty * 8 + i;
        *(float4*)&C[m * NN + n0 + tx * 8]     = make_float4(acc[i][0], acc[i][1], acc[i][2], acc[i][3]);
        *(float4*)&C[m * NN + n0 + tx * 8 + 4] = make_float4(acc[i][4], acc[i][5], acc[i][6], acc[i][7]);
    }
}

// ---------------- launch ----------------
extern "C" void kernel_launch(void* const* d_in, const int* in_sizes, int n_in,
                              void* d_out, int out_size) {
    const float* x     = (const float*)d_in[0];
    const float* phiU  = (const float*)d_in[1];
    const float* dU    = (const float*)d_in[2];
    const float* phiV  = (const float*)d_in[3];
    const float* dV    = (const float*)d_in[4];
    const float* sigma = (const float*)d_in[5];
    float* out = (float*)d_out;

    const int recon_smem = 32 * RSTRIDE * 4 + RINGSZ * 8;   // 66048 + 8192 = 74240 B
    cudaFuncSetAttribute(reconstruct_kernel,
                         cudaFuncAttributeMaxDynamicSharedMemorySize, recon_smem);

    setup_cs_kernel<<<(NPAIRS + 255) / 256, 256>>>(phiU, phiV);
    reconstruct_kernel<<<32, 32, recon_smem>>>(dU, dV, sigma);
    wgemm_kernel<<<dim3(16, 16), dim3(32, 32)>>>();
    sgemm_kernel<<<dim3(NN / 128, 32768 / 128), 256>>>(x, out);
}

// round 3
// speedup vs baseline: 4.2831x; 1.5914x over previous
#include <cuda_runtime.h>

#define NN 512
#define NPAIRS 130816   // 512*511/2
#define CSTRIDE 516     // column stride in smem floats (mult of 4; conflict-free float4 phases)

// ---------------- device scratch (no allocations allowed) ----------------
// Slot layout: pivot i occupies entries [i*512, i*512+512); entry m = rotation
// (i, j=511-m) for m < 511-i, else (c=1,s=0) padding. U at slot 0, V at +262144.
__device__ __align__(16) float2 g_slot[2 * 512 * 512];   // 4 MB
__device__ float g_U [NN * NN];   // delta_U[a] * RU[a][k]
__device__ float g_Vs[NN * NN];   // sigma[k]*delta_V[k]*RV[k][b]
__device__ float g_W [NN * NN];   // W[o][k]

// ---------------- 1) cos/sin precompute into padded slots ----------------
__global__ void setup_cs_kernel(const float* __restrict__ phiU,
                                const float* __restrict__ phiV) {
    int tid = blockIdx.x * blockDim.x + threadIdx.x;
    if (tid >= 2 * 512 * 512) return;
    int mat = tid >> 18;
    int r   = tid & 262143;
    int i   = r >> 9;
    int m   = r & 511;
    float c = 1.0f, s = 0.0f;
    int L = 511 - i;
    if (m < L) {
        int k = i * 511 - (i * (i - 1)) / 2 + m;
        float ph = mat ? __ldg(&phiV[k]) : __ldg(&phiU[k]);
        sincosf(ph, &s, &c);
    }
    g_slot[tid] = make_float2(c, s);
}

// ---------------- 2) Givens-mesh reconstruction ----------------
// One warp per CTA; lane t owns one column resident in smem. cs stream is
// prefetched TWO pivots ahead in registers (LDG latency hidden), staged to a
// smem ring per pivot. Inner loop: 8-step groups, ring + next-group column
// loads issued ahead of the FFMA chain and stores (software pipeline).
#define STEP(u, cc, ss) do { float _t2 = (cc)*(u); float _t1 = (ss)*(u); \
                             (u) = fmaf((ss), A, _t2); A = fmaf((cc), A, -_t1); } while (0)

__device__ __forceinline__ void do_pivot(int i, int t, float4 (&pref)[8],
                                         float* __restrict__ myc,
                                         float2* __restrict__ ring,
                                         const float4* __restrict__ slotf4) {
    float4* ringf4 = (float4*)ring;

    __syncwarp();
    #pragma unroll
    for (int q = 0; q < 8; q++) ringf4[q * 32 + t] = pref[q];   // stage pivot i
    __syncwarp();

    int np = i + 2; if (np > 511) np = 511;                      // prefetch pivot i+2
    #pragma unroll
    for (int q = 0; q < 8; q++) pref[q] = __ldg(&slotf4[np * 256 + q * 32 + t]);

    const int L = 511 - i;
    float A = myc[i];                       // pivot carry (1-FFMA-deep chain)
    const int ngroups = L >> 3;

    if (ngroups > 0) {
        int jtop = 511;
        float4 va = *(float4*)&myc[jtop - 3];    // rows jtop-3..jtop
        float4 vb = *(float4*)&myc[jtop - 7];    // rows jtop-7..jtop-4
        for (int g = 0; g < ngroups; g++, jtop -= 8) {
            const float4 r0 = ringf4[(g << 2) + 0];   // (c0,s0,c1,s1)
            const float4 r1 = ringf4[(g << 2) + 1];
            const float4 r2 = ringf4[(g << 2) + 2];
            const float4 r3 = ringf4[(g << 2) + 3];
            float4 na = va, nb = vb;
            if (g + 1 < ngroups) {                    // prefetch next group's rows
                na = *(float4*)&myc[jtop - 11];
                nb = *(float4*)&myc[jtop - 15];
            }
            // descending j: jtop, jtop-1, ..., jtop-7  ==  m0..m0+7
            STEP(va.w, r0.x, r0.y);
            STEP(va.z, r0.z, r0.w);
            STEP(va.y, r1.x, r1.y);
            STEP(va.x, r1.z, r1.w);
            STEP(vb.w, r2.x, r2.y);
            STEP(vb.z, r2.z, r2.w);
            STEP(vb.y, r3.x, r3.y);
            STEP(vb.x, r3.z, r3.w);
            *(float4*)&myc[jtop - 3] = va;
            *(float4*)&myc[jtop - 7] = vb;
            va = na; vb = nb;
        }
    }
    // remainder (smallest j's, scalar)
    for (int m = ngroups << 3; m < L; m++) {
        float2 p = ring[m];
        int j = 511 - m;
        float u = myc[j];
        float t2 = p.x * u, t1 = p.y * u;
        myc[j] = fmaf(p.y, A, t2);
        A = fmaf(p.x, A, -t1);
    }
    myc[i] = A;
}

__global__ void __launch_bounds__(32) reconstruct_kernel(const float* __restrict__ dU,
                                                         const float* __restrict__ dV,
                                                         const float* __restrict__ sigma) {
    extern __shared__ float sm[];
    float*  cols = sm;                            // 32 * CSTRIDE floats
    float2* ring = (float2*)(sm + 32 * CSTRIDE);  // 512 float2 = 4 KB

    const int mat     = blockIdx.x >> 4;          // 0 = U (CTAs 0..15), 1 = V
    const int colbase = (blockIdx.x & 15) << 5;
    const int t       = threadIdx.x;
    const int col     = colbase + t;

    const float4* slotf4 = (const float4*)(g_slot + mat * 262144);
    float* myc = cols + t * CSTRIDE;

    // identity column
    for (int r = 0; r < NN; r += 4) {
        float4 z = make_float4(0.f, 0.f, 0.f, 0.f);
        if (col >= r && col < r + 4) ((float*)&z)[col - r] = 1.0f;
        *(float4*)&myc[r] = z;
    }

    // prefetch pivots 0 and 1
    float4 prefA[8], prefB[8];
    #pragma unroll
    for (int q = 0; q < 8; q++) prefA[q] = __ldg(&slotf4[0 * 256 + q * 32 + t]);
    #pragma unroll
    for (int q = 0; q < 8; q++) prefB[q] = __ldg(&slotf4[1 * 256 + q * 32 + t]);

    for (int i = 0; i < 511; i += 2) {
        do_pivot(i, t, prefA, myc, ring, slotf4);
        if (i + 1 < 511) do_pivot(i + 1, t, prefB, myc, ring, slotf4);
    }

    // scale + write back row-major (coalesced across lanes)
    if (mat == 0) {
        for (int r = 0; r < NN; r++)
            g_U[r * NN + col] = __ldg(&dU[r]) * myc[r];
    } else {
        for (int r = 0; r < NN; r++)
            g_Vs[r * NN + col] = __ldg(&sigma[r]) * __ldg(&dV[r]) * myc[r];
    }
}

// ---------------- 3) W = U @ (sigma*delta_V * V)   (512x512x512, tiny) ----------------
__global__ void wgemm_kernel() {
    __shared__ float As[32][33];
    __shared__ float Bs[32][33];
    const int tx = threadIdx.x, ty = threadIdx.y;
    const int a = blockIdx.y * 32 + ty;
    const int b = blockIdx.x * 32 + tx;
    float acc = 0.0f;
    for (int kt = 0; kt < NN; kt += 32) {
        As[ty][tx] = g_U [a * NN + kt + tx];
        Bs[ty][tx] = g_Vs[(kt + ty) * NN + b];
        __syncthreads();
        #pragma unroll
        for (int kk = 0; kk < 32; kk++)
            acc += As[ty][kk] * Bs[kk][tx];
        __syncthreads();
    }
    g_W[a * NN + b] = acc;
}

// ---------------- 4) out = x @ W^T  (M=32768, N=512, K=512, fp32) ----------------
__global__ void __launch_bounds__(256) sgemm_kernel(const float* __restrict__ A,
                                                    float* __restrict__ C) {
    __shared__ float As[16][132];
    __shared__ float Bs[16][132];
    const float* __restrict__ B = g_W;

    const int tid = threadIdx.x;
    const int m0  = blockIdx.y * 128;
    const int n0  = blockIdx.x * 128;
    const int tx  = tid & 15;
    const int ty  = tid >> 4;
    const int lrow = tid >> 2;
    const int lcol = (tid & 3) << 2;

    const float* Ap = A + (m0 + lrow) * NN + lcol;
    const float* Bp = B + (n0 + lrow) * NN + lcol;

    float acc[8][8];
    #pragma unroll
    for (int i = 0; i < 8; i++)
        #pragma unroll
        for (int j = 0; j < 8; j++) acc[i][j] = 0.0f;

    for (int k0 = 0; k0 < NN; k0 += 16) {
        float4 a0 = *(const float4*)(Ap + k0);
        float4 a1 = *(const float4*)(Ap + 64 * NN + k0);
        float4 b0 = *(const float4*)(Bp + k0);
        float4 b1 = *(const float4*)(Bp + 64 * NN + k0);

        As[lcol + 0][lrow]      = a0.x; As[lcol + 1][lrow]      = a0.y;
        As[lcol + 2][lrow]      = a0.z; As[lcol + 3][lrow]      = a0.w;
        As[lcol + 0][lrow + 64] = a1.x; As[lcol + 1][lrow + 64] = a1.y;
        As[lcol + 2][lrow + 64] = a1.z; As[lcol + 3][lrow + 64] = a1.w;
        Bs[lcol + 0][lrow]      = b0.x; Bs[lcol + 1][lrow]      = b0.y;
        Bs[lcol + 2][lrow]      = b0.z; Bs[lcol + 3][lrow]      = b0.w;
        Bs[lcol + 0][lrow + 64] = b1.x; Bs[lcol + 1][lrow + 64] = b1.y;
        Bs[lcol + 2][lrow + 64] = b1.z; Bs[lcol + 3][lrow + 64] = b1.w;
        __syncthreads();

        #pragma unroll
        for (int kk = 0; kk < 16; kk++) {
            float4 av0 = *(const float4*)&As[kk][ty * 8];
            float4 av1 = *(const float4*)&As[kk][ty * 8 + 4];
            float4 bv0 = *(const float4*)&Bs[kk][tx * 8];
            float4 bv1 = *(const float4*)&Bs[kk][tx * 8 + 4];
            float a[8] = {av0.x, av0.y, av0.z, av0.w, av1.x, av1.y, av1.z, av1.w};
            float b[8] = {bv0.x, bv0.y, bv0.z, bv0.w, bv1.x, bv1.y, bv1.z, bv1.w};
            #pragma unroll
            for (int i = 0; i < 8; i++)
                #pragma unroll
                for (int j = 0; j < 8; j++)
                    acc[i][j] += a[i] * b[j];
        }
        __syncthreads();
    }

    #pragma unroll
    for (int i = 0; i < 8; i++) {
        int m = m0 + ty * 8 + i;
        *(float4*)&C[m * NN + n0 + tx * 8]     = make_float4(acc[i][0], acc[i][1], acc[i][2], acc[i][3]);
        *(float4*)&C[m * NN + n0 + tx * 8 + 4] = make_float4(acc[i][4], acc[i][5], acc[i][6], acc[i][7]);
    }
}

// ---------------- launch ----------------
extern "C" void kernel_launch(void* const* d_in, const int* in_sizes, int n_in,
                              void* d_out, int out_size) {
    const float* x     = (const float*)d_in[0];
    const float* phiU  = (const float*)d_in[1];
    const float* dU    = (const float*)d_in[2];
    const float* phiV  = (const float*)d_in[3];
    const float* dV    = (const float*)d_in[4];
    const float* sigma = (const float*)d_in[5];
    float* out = (float*)d_out;

    const int recon_smem = 32 * CSTRIDE * 4 + 512 * 8;   // 66048 + 4096 = 70144 B
    cudaFuncSetAttribute(reconstruct_kernel,
                         cudaFuncAttributeMaxDynamicSharedMemorySize, recon_smem);

    setup_cs_kernel<<<(2 * 512 * 512 + 255) / 256, 256>>>(phiU, phiV);
    reconstruct_kernel<<<32, 32, recon_smem>>>(dU, dV, sigma);
    wgemm_kernel<<<dim3(16, 16), dim3(32, 32)>>>();
    sgemm_kernel<<<dim3(NN / 128, 32768 / 128), 256>>>(x, out);
}

// round 4
// speedup vs baseline: 5.0473x; 1.1784x over previous
#include <cuda_runtime.h>

#define NN 512
#define RST 516          // column stride (floats); float4 phases conflict-free

// ---------------- device scratch (no allocations allowed) ----------------
// Slot layout: pivot i occupies entries [i*512, i*512+512); entry m = rotation
// (i, j=511-m) for m < 511-i, else (c=1,s=0) padding. U at 0, V at +262144.
__device__ __align__(16) float2 g_slot[2 * 512 * 512];   // 4 MB
__device__ float g_U [NN * NN];
__device__ float g_Vs[NN * NN];
__device__ float g_W [NN * NN];

// ---------------- 1) cos/sin precompute into padded slots ----------------
__global__ void setup_cs_kernel(const float* __restrict__ phiU,
                                const float* __restrict__ phiV) {
    int tid = blockIdx.x * blockDim.x + threadIdx.x;
    if (tid >= 2 * 512 * 512) return;
    int mat = tid >> 18;
    int r   = tid & 262143;
    int i   = r >> 9;
    int m   = r & 511;
    float c = 1.0f, s = 0.0f;
    if (m < 511 - i) {
        int k = i * 511 - (i * (i - 1)) / 2 + m;
        float ph = mat ? __ldg(&phiV[k]) : __ldg(&phiU[k]);
        sincosf(ph, &s, &c);
    }
    g_slot[tid] = make_float2(c, s);
}

// ---------------- 2) Givens-mesh reconstruction, 4-warp chain-split ----------------
// 128 threads/CTA. Lane l owns column (colbase+l) in smem, shared by 4 warps.
// Per pivot: warp w handles m-chunk [w*Lc, min(L,(w+1)*Lc)).
// Phase 1: chunk-local C = prod(c), D with D <- c*D + s*u  (no writes).
// Stitch:  A_in[w] = fold of (C,D) of lower chunks applied to A0 = myc[i].
// Phase 2: replay chunk: u' = s*A + c*u ; A = c*A - s*u.
// Warp 3 writes myc[i] = C3*A_in3 - D3 during stitch.

#define P2STEP(u, cc, ss) do { float _t2 = (cc)*(u); float _t1 = (ss)*(u); \
                               (u) = fmaf((ss), A, _t2); A = fmaf((cc), A, -_t1); } while (0)
#define P1STEP(u, cc, ss) do { Dw = fmaf((cc), Dw, (ss)*(u)); Cw = (cc)*Cw; } while (0)

__global__ void __launch_bounds__(128) reconstruct_kernel(const float* __restrict__ dU,
                                                          const float* __restrict__ dV,
                                                          const float* __restrict__ sigma) {
    extern __shared__ float sm[];
    float*  cols  = sm;                               // 32*RST floats
    float2* ring0 = (float2*)(sm + 32 * RST);         // 2 x 512 float2 (double buffer)
    float*  Csh   = (float*)(ring0 + 1024);           // 4
    float*  Dsh   = Csh + 4;                          // 4 x 32

    const int mat     = blockIdx.x >> 4;
    const int colbase = (blockIdx.x & 15) << 5;
    const int tid  = threadIdx.x;
    const int w    = tid >> 5;
    const int lane = tid & 31;
    const int col  = colbase + lane;

    const float4* slotf4 = (const float4*)(g_slot + mat * 262144);
    float* myc = cols + lane * RST;

    // identity columns: warp w fills rows [w*128, w*128+128)
    for (int r = w * 128; r < w * 128 + 128; r += 4) {
        float4 z = make_float4(0.f, 0.f, 0.f, 0.f);
        if (col >= r && col < r + 4) ((float*)&z)[col - r] = 1.0f;
        *(float4*)&myc[r] = z;
    }

    // cs prefetch: pivots 0 and 1 (2 float4 per thread per pivot)
    float4 pA0 = __ldg(&slotf4[tid]);
    float4 pA1 = __ldg(&slotf4[128 + tid]);
    float4 pB0 = __ldg(&slotf4[256 + tid]);
    float4 pB1 = __ldg(&slotf4[256 + 128 + tid]);

    for (int i = 0; i < 511; i++) {
        // stage ring for pivot i (parity i&1), prefetch pivot i+2
        float4* rq = (float4*)(ring0 + (i & 1) * 512);
        rq[tid]       = pA0;
        rq[tid + 128] = pA1;
        pA0 = pB0; pA1 = pB1;
        int np = (i + 2 <= 511) ? i + 2 : 511;
        pB0 = __ldg(&slotf4[np * 256 + tid]);
        pB1 = __ldg(&slotf4[np * 256 + 128 + tid]);
        __syncthreads();   // ring visible; previous pivot phase2 done

        const float2* ringp = ring0 + (i & 1) * 512;
        const float4* rf    = (const float4*)ringp;

        const int L  = 511 - i;
        int Lc = (((L + 3) >> 2) + 7) & ~7;           // chunk size, multiple of 8
        int m0 = w * Lc;
        int m1 = m0 + Lc; if (m1 > L) m1 = L; if (m0 > L) m0 = L;

        const float A0 = myc[i];
        float Cw = 1.0f, Dw = 0.0f;

        // ---- phase 1 ----
        {
            int nfull = (m1 - m0) >> 3;
            int m = m0;
            if (nfull > 0) {
                int j = 511 - m;
                float4 va = *(float4*)&myc[j - 3];
                float4 vb = *(float4*)&myc[j - 7];
                float4 r0 = rf[(m >> 1) + 0], r1 = rf[(m >> 1) + 1];
                float4 r2 = rf[(m >> 1) + 2], r3 = rf[(m >> 1) + 3];
                for (int g = 0; g < nfull; g++) {
                    float4 nva = va, nvb = vb, n0 = r0, n1 = r1, n2 = r2, n3 = r3;
                    if (g + 1 < nfull) {
                        int mn = m + 8, jn = 511 - mn;
                        n0 = rf[(mn >> 1) + 0]; n1 = rf[(mn >> 1) + 1];
                        n2 = rf[(mn >> 1) + 2]; n3 = rf[(mn >> 1) + 3];
                        nva = *(float4*)&myc[jn - 3];
                        nvb = *(float4*)&myc[jn - 7];
                    }
                    P1STEP(va.w, r0.x, r0.y);  P1STEP(va.z, r0.z, r0.w);
                    P1STEP(va.y, r1.x, r1.y);  P1STEP(va.x, r1.z, r1.w);
                    P1STEP(vb.w, r2.x, r2.y);  P1STEP(vb.z, r2.z, r2.w);
                    P1STEP(vb.y, r3.x, r3.y);  P1STEP(vb.x, r3.z, r3.w);
                    va = nva; vb = nvb; r0 = n0; r1 = n1; r2 = n2; r3 = n3;
                    m += 8;
                }
            }
            for (; m < m1; m++) {
                float2 p = ringp[m];
                float  u = myc[511 - m];
                Dw = fmaf(p.x, Dw, p.y * u);
                Cw = p.x * Cw;
            }
        }

        // ---- stitch ----
        if (lane == 0) Csh[w] = Cw;
        Dsh[w * 32 + lane] = Dw;
        __syncthreads();
        float A = A0;
        if (w > 0) A = fmaf(Csh[0], A, -Dsh[0 * 32 + lane]);
        if (w > 1) A = fmaf(Csh[1], A, -Dsh[1 * 32 + lane]);
        if (w > 2) A = fmaf(Csh[2], A, -Dsh[2 * 32 + lane]);
        if (w == 3) myc[i] = fmaf(Cw, A, -Dw);        // final pivot value

        // ---- phase 2 ----
        {
            int nfull = (m1 - m0) >> 3;
            int m = m0;
            if (nfull > 0) {
                int j = 511 - m;
                float4 va = *(float4*)&myc[j - 3];
                float4 vb = *(float4*)&myc[j - 7];
                float4 r0 = rf[(m >> 1) + 0], r1 = rf[(m >> 1) + 1];
                float4 r2 = rf[(m >> 1) + 2], r3 = rf[(m >> 1) + 3];
                for (int g = 0; g < nfull; g++) {
                    float4 nva = va, nvb = vb, n0 = r0, n1 = r1, n2 = r2, n3 = r3;
                    if (g + 1 < nfull) {
                        int mn = m + 8, jn = 511 - mn;
                        n0 = rf[(mn >> 1) + 0]; n1 = rf[(mn >> 1) + 1];
                        n2 = rf[(mn >> 1) + 2]; n3 = rf[(mn >> 1) + 3];
                        nva = *(float4*)&myc[jn - 3];
                        nvb = *(float4*)&myc[jn - 7];
                    }
                    P2STEP(va.w, r0.x, r0.y);  P2STEP(va.z, r0.z, r0.w);
                    P2STEP(va.y, r1.x, r1.y);  P2STEP(va.x, r1.z, r1.w);
                    P2STEP(vb.w, r2.x, r2.y);  P2STEP(vb.z, r2.z, r2.w);
                    P2STEP(vb.y, r3.x, r3.y);  P2STEP(vb.x, r3.z, r3.w);
                    int jj = 511 - m;
                    *(float4*)&myc[jj - 3] = va;
                    *(float4*)&myc[jj - 7] = vb;
                    va = nva; vb = nvb; r0 = n0; r1 = n1; r2 = n2; r3 = n3;
                    m += 8;
                }
            }
            for (; m < m1; m++) {
                float2 p = ringp[m];
                int jj = 511 - m;
                float u = myc[jj];
                float t2 = p.x * u, t1 = p.y * u;
                myc[jj] = fmaf(p.y, A, t2);
                A = fmaf(p.x, A, -t1);
            }
        }
        // next pivot's __syncthreads orders phase2 writes before phase1 reads
    }
    __syncthreads();

    // writeback: warp w rows [w*128, w*128+128), coalesced across lanes
    if (mat == 0) {
        for (int r = w * 128; r < w * 128 + 128; r++)
            g_U[r * NN + col] = __ldg(&dU[r]) * myc[r];
    } else {
        for (int r = w * 128; r < w * 128 + 128; r++)
            g_Vs[r * NN + col] = __ldg(&sigma[r]) * __ldg(&dV[r]) * myc[r];
    }
}

// ---------------- 3) W = U @ (sigma*delta_V * V) ----------------
__global__ void wgemm_kernel() {
    __shared__ float As[32][33];
    __shared__ float Bs[32][33];
    const int tx = threadIdx.x, ty = threadIdx.y;
    const int a = blockIdx.y * 32 + ty;
    const int b = blockIdx.x * 32 + tx;
    float acc = 0.0f;
    for (int kt = 0; kt < NN; kt += 32) {
        As[ty][tx] = g_U [a * NN + kt + tx];
        Bs[ty][tx] = g_Vs[(kt + ty) * NN + b];
        __syncthreads();
        #pragma unroll
        for (int kk = 0; kk < 32; kk++)
            acc += As[ty][kk] * Bs[kk][tx];
        __syncthreads();
    }
    g_W[a * NN + b] = acc;
}

// ---------------- 4) out = x @ W^T, double-buffered smem ----------------
__global__ void __launch_bounds__(256) sgemm_kernel(const float* __restrict__ A,
                                                    float* __restrict__ C) {
    __shared__ float As[2][16][132];
    __shared__ float Bs[2][16][132];
    const float* __restrict__ B = g_W;

    const int tid = threadIdx.x;
    const int m0  = blockIdx.y * 128;
    const int n0  = blockIdx.x * 128;
    const int tx  = tid & 15;
    const int ty  = tid >> 4;
    const int lrow = tid >> 2;
    const int lcol = (tid & 3) << 2;

    const float* Ap = A + (m0 + lrow) * NN + lcol;
    const float* Bp = B + (n0 + lrow) * NN + lcol;

    float acc[8][8];
    #pragma unroll
    for (int i = 0; i < 8; i++)
        #pragma unroll
        for (int j = 0; j < 8; j++) acc[i][j] = 0.0f;

    float4 a0, a1, b0, b1;

    #define LOAD_TILE(k0) do { \
        a0 = *(const float4*)(Ap + (k0)); \
        a1 = *(const float4*)(Ap + 64 * NN + (k0)); \
        b0 = *(const float4*)(Bp + (k0)); \
        b1 = *(const float4*)(Bp + 64 * NN + (k0)); } while (0)

    #define STORE_TILE(bf) do { \
        As[bf][lcol + 0][lrow]      = a0.x; As[bf][lcol + 1][lrow]      = a0.y; \
        As[bf][lcol + 2][lrow]      = a0.z; As[bf][lcol + 3][lrow]      = a0.w; \
        As[bf][lcol + 0][lrow + 64] = a1.x; As[bf][lcol + 1][lrow + 64] = a1.y; \
        As[bf][lcol + 2][lrow + 64] = a1.z; As[bf][lcol + 3][lrow + 64] = a1.w; \
        Bs[bf][lcol + 0][lrow]      = b0.x; Bs[bf][lcol + 1][lrow]      = b0.y; \
        Bs[bf][lcol + 2][lrow]      = b0.z; Bs[bf][lcol + 3][lrow]      = b0.w; \
        Bs[bf][lcol + 0][lrow + 64] = b1.x; Bs[bf][lcol + 1][lrow + 64] = b1.y; \
        Bs[bf][lcol + 2][lrow + 64] = b1.z; Bs[bf][lcol + 3][lrow + 64] = b1.w; } while (0)

    #define COMPUTE(bf) do { \
        _Pragma("unroll") \
        for (int kk = 0; kk < 16; kk++) { \
            float4 av0 = *(const float4*)&As[bf][kk][ty * 8]; \
            float4 av1 = *(const float4*)&As[bf][kk][ty * 8 + 4]; \
            float4 bv0 = *(const float4*)&Bs[bf][kk][tx * 8]; \
            float4 bv1 = *(const float4*)&Bs[bf][kk][tx * 8 + 4]; \
            float a_[8] = {av0.x, av0.y, av0.z, av0.w, av1.x, av1.y, av1.z, av1.w}; \
            float b_[8] = {bv0.x, bv0.y, bv0.z, bv0.w, bv1.x, bv1.y, bv1.z, bv1.w}; \
            _Pragma("unroll") \
            for (int ii = 0; ii < 8; ii++) \
                _Pragma("unroll") \
                for (int jj = 0; jj < 8; jj++) \
                    acc[ii][jj] += a_[ii] * b_[jj]; \
        } } while (0)

    LOAD_TILE(0);
    STORE_TILE(0);
    __syncthreads();
    int buf = 0;
    for (int k0 = 16; k0 < NN; k0 += 16) {
        LOAD_TILE(k0);
        COMPUTE(buf);
        STORE_TILE(buf ^ 1);
        __syncthreads();
        buf ^= 1;
    }
    COMPUTE(buf);

    #pragma unroll
    for (int i = 0; i < 8; i++) {
        int m = m0 + ty * 8 + i;
        *(float4*)&C[m * NN + n0 + tx * 8]     = make_float4(acc[i][0], acc[i][1], acc[i][2], acc[i][3]);
        *(float4*)&C[m * NN + n0 + tx * 8 + 4] = make_float4(acc[i][4], acc[i][5], acc[i][6], acc[i][7]);
    }
}

// ---------------- launch ----------------
extern "C" void kernel_launch(void* const* d_in, const int* in_sizes, int n_in,
                              void* d_out, int out_size) {
    const float* x     = (const float*)d_in[0];
    const float* phiU  = (const float*)d_in[1];
    const float* dU    = (const float*)d_in[2];
    const float* phiV  = (const float*)d_in[3];
    const float* dV    = (const float*)d_in[4];
    const float* sigma = (const float*)d_in[5];
    float* out = (float*)d_out;

    const int recon_smem = 32 * RST * 4 + 1024 * 8 + (4 + 128) * 4;   // 74768 B
    cudaFuncSetAttribute(reconstruct_kernel,
                         cudaFuncAttributeMaxDynamicSharedMemorySize, recon_smem);

    setup_cs_kernel<<<(2 * 512 * 512 + 255) / 256, 256>>>(phiU, phiV);
    reconstruct_kernel<<<32, 128, recon_smem>>>(dU, dV, sigma);
    wgemm_kernel<<<dim3(16, 16), dim3(32, 32)>>>();
    sgemm_kernel<<<dim3(NN / 128, 32768 / 128), 256>>>(x, out);
}